// round 8
// baseline (speedup 1.0000x reference)
#include <cuda_runtime.h>
#include <cuda_bf16.h>
#include <cstdint>
#include <cstddef>

// ---------------------------------------------------------------------------
// SupervisedTEMTransition on GB300 (sm_103a), round 5.
//
// R3/R4 analysis: cls GEMM was SMEM-port bound (LDS fragment re-reads + STS
// = ~1875 cyc/chunk vs 1024 tensor cyc -> tensor pinned at ~55%).
// R5: CTA tile 256x128, 8 warps as 4(M) x 2(N) of 64x64 warp tiles:
//   A re-read 2x (was 4x) -> smem 1375 cyc/chunk vs tensor 2048 cyc.
//   Tensor pipe becomes the binder (predicted ~85%).
// bin/trans/wround unchanged.
// ---------------------------------------------------------------------------

#define BATCH_MAX   16384
#define G_TOTAL     768
#define NUM_STATES  4096
#define N_ACTIONS   4

__device__ int   d_perm[BATCH_MAX];
__device__ int   d_off[N_ACTIONS + 1];
__device__ float d_gnext[(size_t)BATCH_MAX * G_TOTAL];       // tf32-rounded A
__device__ float d_wtf32[(size_t)NUM_STATES * G_TOTAL];      // tf32-rounded W

__device__ __forceinline__ uint32_t smem_u32(const void* p) {
    uint32_t a;
    asm("{ .reg .u64 t; cvta.to.shared.u64 t, %1; cvt.u32.u64 %0, t; }"
        : "=r"(a) : "l"(p));
    return a;
}

__device__ __forceinline__ float tf32_rna(float x) {
    float r;
    asm("cvt.rna.tf32.f32 %0, %1;" : "=f"(r) : "f"(x));
    return r;
}

// ---------------------------------------------------------------------------
// Kernel 1: bin rows by action
// ---------------------------------------------------------------------------
__global__ void bin_kernel(const int* __restrict__ act, int B) {
    __shared__ int cnt[N_ACTIONS];
    __shared__ int base[N_ACTIONS];
    int t = threadIdx.x;
    if (t < N_ACTIONS) cnt[t] = 0;
    __syncthreads();
    for (int b = t; b < B; b += blockDim.x) atomicAdd(&cnt[act[b]], 1);
    __syncthreads();
    if (t == 0) {
        int s = 0;
        for (int a = 0; a < N_ACTIONS; a++) { base[a] = s; d_off[a] = s; s += cnt[a]; }
        d_off[N_ACTIONS] = s;
    }
    __syncthreads();
    if (t < N_ACTIONS) cnt[t] = 0;
    __syncthreads();
    for (int b = t; b < B; b += blockDim.x) {
        int a = act[b];
        int p = base[a] + atomicAdd(&cnt[a], 1);
        d_perm[p] = b;
    }
}

// ---------------------------------------------------------------------------
// Kernel 2: routed transition (fp32-exact math; dual-write epilogue)
// ---------------------------------------------------------------------------
__global__ __launch_bounds__(256)
void trans_kernel(const float* __restrict__ emb,
                  const int*   __restrict__ state,
                  const float* __restrict__ D0, const float* __restrict__ D1,
                  const float* __restrict__ D2, const float* __restrict__ D3,
                  float* __restrict__ gdst,      // tf32-rounded scratch
                  float* __restrict__ gout,      // exact fp32 d_out tail
                  int B)
{
    __shared__ float Gs[16][68];
    __shared__ float Ds[16][68];
    __shared__ int   srow[64];
    __shared__ int   sb[64];

    const int a = blockIdx.z >> 2;
    const int f = blockIdx.z & 3;
    const int nf   = (f < 2) ? 256 : 128;
    const int moff = (f == 0) ? 0 : (f == 1) ? 256 : (f == 2) ? 512 : 640;
    const int j0 = blockIdx.x * 64;
    if (j0 >= nf) return;
    const int start = d_off[a];
    const int cnt   = d_off[a + 1] - start;
    const int r0 = blockIdx.y * 64;
    if (r0 >= cnt) return;

    const float* Dbank = (f == 0) ? D0 : (f == 1) ? D1 : (f == 2) ? D2 : D3;
    const float* Dm = Dbank + (size_t)a * nf * nf;

    const int tid = threadIdx.x;
    if (tid < 64) {
        int rr = r0 + tid;
        if (rr < cnt) {
            int bidx = d_perm[start + rr];
            sb[tid]   = bidx;
            srow[tid] = state[bidx] * G_TOTAL;
        } else {
            sb[tid] = -1; srow[tid] = -1;
        }
    }
    __syncthreads();

    const int lm  = tid >> 2;
    const int lk4 = (tid & 3) * 4;
    const int tr  = tid >> 4;
    const int tc  = tid & 15;

    float acc[4][4] = {};

    for (int k0 = 0; k0 < nf; k0 += 16) {
        float4 gv = make_float4(0.f, 0.f, 0.f, 0.f);
        int sr = srow[lm];
        if (sr >= 0)
            gv = *(const float4*)(emb + sr + moff + k0 + lk4);
        float4 dv = *(const float4*)(Dm + (size_t)(j0 + lm) * nf + k0 + lk4);

        Gs[lk4 + 0][lm] = gv.x; Gs[lk4 + 1][lm] = gv.y;
        Gs[lk4 + 2][lm] = gv.z; Gs[lk4 + 3][lm] = gv.w;
        Ds[lk4 + 0][lm] = dv.x; Ds[lk4 + 1][lm] = dv.y;
        Ds[lk4 + 2][lm] = dv.z; Ds[lk4 + 3][lm] = dv.w;
        __syncthreads();

        #pragma unroll
        for (int k = 0; k < 16; k++) {
            float4 av = *(const float4*)&Gs[k][tr * 4];
            float4 bv = *(const float4*)&Ds[k][tc * 4];
            float ar[4] = {av.x, av.y, av.z, av.w};
            float br[4] = {bv.x, bv.y, bv.z, bv.w};
            #pragma unroll
            for (int i = 0; i < 4; i++)
                #pragma unroll
                for (int j = 0; j < 4; j++)
                    acc[i][j] = fmaf(ar[i], br[j], acc[i][j]);
        }
        __syncthreads();
    }

    #pragma unroll
    for (int i = 0; i < 4; i++) {
        int m = tr * 4 + i;
        int bidx = sb[m];
        if (bidx < 0) continue;
        const float* grow = emb + srow[m] + moff + j0 + tc * 4;
        size_t obase = (size_t)bidx * G_TOTAL + moff + j0 + tc * 4;
        #pragma unroll
        for (int j = 0; j < 4; j++) {
            float v = grow[j] + acc[i][j];
            v = fminf(fmaxf(v, -1.0f), 1.0f);
            gdst[obase + j] = tf32_rna(v);
            if (gout) gout[obase + j] = v;
        }
    }
}

// ---------------------------------------------------------------------------
// Kernel 3: tf32-round W
// ---------------------------------------------------------------------------
__global__ __launch_bounds__(256)
void wround_kernel(const float* __restrict__ W, float* __restrict__ Wo) {
    int i = (blockIdx.x * 256 + threadIdx.x) * 4;
    float4 v = *(const float4*)(W + i);
    v.x = tf32_rna(v.x); v.y = tf32_rna(v.y);
    v.z = tf32_rna(v.z); v.w = tf32_rna(v.w);
    *(float4*)(Wo + i) = v;
}

// ---------------------------------------------------------------------------
// Kernel 4: tf32 mma.sync classifier GEMM.
//   CTA tile 256(M) x 128(N); 8 warps = 4(M) x 2(N) of 64x64 warp tiles.
//   K chunks of 32, 3-stage cp.async ring, one __syncthreads per chunk.
// ---------------------------------------------------------------------------
#define AKP          36                       // padded row length (floats)
#define A_FLOATS     (256 * AKP)              // 9216
#define B_FLOATS     (128 * AKP)              // 4608
#define STAGE_FLOATS (A_FLOATS + B_FLOATS)    // 13824 floats (55296 B)
#define STAGES       3
#define CHUNKS       24
#define CLS_DYN_SMEM (STAGES * STAGE_FLOATS * 4)   // 165888 B

extern __shared__ float cls_sm[];

__device__ __forceinline__ void cp16(uint32_t saddr, const float* g) {
    asm volatile("cp.async.cg.shared.global [%0], [%1], 16;"
                 :: "r"(saddr), "l"(g) : "memory");
}

__global__ __launch_bounds__(256, 1)
void cls_mma_kernel(const float* __restrict__ A,     // [16384,768] tf32-rounded
                    const float* __restrict__ W,     // [4096,768] tf32-rounded
                    const float* __restrict__ bias,
                    float* __restrict__ C)
{
    __shared__ float bias_s[128];

    const int tid = threadIdx.x;
    const int n0 = blockIdx.x * 128;
    const int m0 = blockIdx.y * 256;

    if (tid < 128) bias_s[tid] = bias[n0 + tid];

    const int lane = tid & 31;
    const int wid  = tid >> 5;
    const int g    = lane >> 2;       // groupID 0..7
    const int tg   = lane & 3;        // threadID_in_group 0..3
    const int wm   = (wid >> 1) * 64; // warp M offset 0/64/128/192
    const int wn   = (wid & 1) * 64;  // warp N offset 0/64

    // cp.async map: A 2048 float4 (8/thread), B 1024 float4 (4/thread)
    const int lrow = tid >> 3;        // 0..31
    const int lcol = tid & 7;         // 0..7
    const float* gA = A + (size_t)(m0 + lrow) * G_TOTAL + lcol * 4;
    const float* gB = W + (size_t)(n0 + lrow) * G_TOTAL + lcol * 4;
    const uint32_t sA0 = lrow * AKP + lcol * 4;            // floats
    const uint32_t sB0 = A_FLOATS + sA0;

    const uint32_t sbase = smem_u32(cls_sm);

    #define ISSUE_CHUNK(c)                                                     \
        do {                                                                   \
            uint32_t _st = sbase + ((c) % STAGES) * (STAGE_FLOATS * 4);        \
            _Pragma("unroll")                                                  \
            for (int i = 0; i < 8; i++)                                        \
                cp16(_st + (sA0 + i * 32 * AKP) * 4,                           \
                     gA + (size_t)i * 32 * G_TOTAL + (c) * 32);                \
            _Pragma("unroll")                                                  \
            for (int i = 0; i < 4; i++)                                        \
                cp16(_st + (sB0 + i * 32 * AKP) * 4,                           \
                     gB + (size_t)i * 32 * G_TOTAL + (c) * 32);                \
            asm volatile("cp.async.commit_group;" ::: "memory");               \
        } while (0)

    ISSUE_CHUNK(0);
    ISSUE_CHUNK(1);

    float acc[4][8][4] = {};   // [mt 16-row][nt 8-col][frag]

    for (int c = 0; c < CHUNKS; c++) {
        if (c < CHUNKS - 1)
            asm volatile("cp.async.wait_group 1;" ::: "memory");
        else
            asm volatile("cp.async.wait_group 0;" ::: "memory");
        __syncthreads();

        if (c + 2 < CHUNKS)
            ISSUE_CHUNK(c + 2);

        const float* sAp = cls_sm + (c % STAGES) * STAGE_FLOATS;
        const float* sBp = sAp + A_FLOATS;

        #pragma unroll
        for (int ks = 0; ks < 4; ks++) {
            uint32_t a[4][4];
            #pragma unroll
            for (int mt = 0; mt < 4; mt++) {
                const uint32_t* ap =
                    (const uint32_t*)(sAp + (wm + mt * 16 + g) * AKP + ks * 8 + tg);
                a[mt][0] = ap[0];
                a[mt][1] = ap[8 * AKP];
                a[mt][2] = ap[4];
                a[mt][3] = ap[8 * AKP + 4];
            }
            uint32_t b[8][2];
            #pragma unroll
            for (int nt = 0; nt < 8; nt++) {
                const uint32_t* bp =
                    (const uint32_t*)(sBp + (wn + nt * 8 + g) * AKP + ks * 8 + tg);
                b[nt][0] = bp[0];
                b[nt][1] = bp[4];
            }
            #pragma unroll
            for (int mt = 0; mt < 4; mt++)
                #pragma unroll
                for (int nt = 0; nt < 8; nt++) {
                    asm volatile(
                        "mma.sync.aligned.m16n8k8.row.col.f32.tf32.tf32.f32 "
                        "{%0,%1,%2,%3}, {%4,%5,%6,%7}, {%8,%9}, {%0,%1,%2,%3};"
                        : "+f"(acc[mt][nt][0]), "+f"(acc[mt][nt][1]),
                          "+f"(acc[mt][nt][2]), "+f"(acc[mt][nt][3])
                        : "r"(a[mt][0]), "r"(a[mt][1]), "r"(a[mt][2]), "r"(a[mt][3]),
                          "r"(b[nt][0]), "r"(b[nt][1]));
                }
        }
    }
    #undef ISSUE_CHUNK

    // epilogue: bias + store
    #pragma unroll
    for (int mt = 0; mt < 4; mt++) {
        int r_lo = m0 + wm + mt * 16 + g;
        float* C0 = C + (size_t)r_lo * NUM_STATES + n0;
        float* C1 = C + (size_t)(r_lo + 8) * NUM_STATES + n0;
        #pragma unroll
        for (int nt = 0; nt < 8; nt++) {
            int nc = wn + nt * 8 + tg * 2;
            float b0 = bias_s[nc], b1 = bias_s[nc + 1];
            *(float2*)(C0 + nc) = make_float2(acc[mt][nt][0] + b0, acc[mt][nt][1] + b1);
            *(float2*)(C1 + nc) = make_float2(acc[mt][nt][2] + b0, acc[mt][nt][3] + b1);
        }
    }
}

// ---------------------------------------------------------------------------
// Launch
// ---------------------------------------------------------------------------
extern "C" void kernel_launch(void* const* d_in, const int* in_sizes, int n_in,
                              void* d_out, int out_size)
{
    const int*   state = (const int*)d_in[0];
    const int*   act   = (const int*)d_in[1];
    const float* emb   = (const float*)d_in[2];

    const float *D0, *D1, *D2, *D3, *W, *bias;
    if (in_sizes[3] == NUM_STATES * G_TOTAL) {
        W  = (const float*)d_in[3];
        bias = (const float*)d_in[4];
        D0 = (const float*)d_in[5];
        D1 = (const float*)d_in[6];
        D2 = (const float*)d_in[7];
        D3 = (const float*)d_in[8];
    } else {
        D0 = (const float*)d_in[3];
        D1 = (const float*)d_in[4];
        D2 = (const float*)d_in[5];
        D3 = (const float*)d_in[6];
        W  = (const float*)d_in[7];
        bias = (const float*)d_in[8];
    }

    const int B = in_sizes[0];
    float* out = (float*)d_out;

    float* logits = out;
    float* gout = nullptr;
    if ((size_t)out_size >= (size_t)B * (NUM_STATES + G_TOTAL))
        gout = out + (size_t)B * NUM_STATES;

    float* gnext_ptr = nullptr;
    float* wtf_ptr = nullptr;
    cudaGetSymbolAddress((void**)&gnext_ptr, d_gnext);
    cudaGetSymbolAddress((void**)&wtf_ptr, d_wtf32);

    cudaFuncSetAttribute(cls_mma_kernel,
                         cudaFuncAttributeMaxDynamicSharedMemorySize, CLS_DYN_SMEM);

    // 1) bin rows by action
    bin_kernel<<<1, 1024>>>(act, B);

    // 2) routed transition -> exact g_next (out tail) + tf32-rounded scratch
    {
        dim3 grid(4, (B + 63) / 64, 16);
        trans_kernel<<<grid, 256>>>(emb, state, D0, D1, D2, D3,
                                    gnext_ptr, gout, B);
    }

    // 3) tf32-round W
    wround_kernel<<<(NUM_STATES * G_TOTAL / 4) / 256, 256>>>(W, wtf_ptr);

    // 4) tf32 tensor-core classifier GEMM
    {
        dim3 grid(NUM_STATES / 128, B / 256);
        cls_mma_kernel<<<grid, 256, CLS_DYN_SMEM>>>(gnext_ptr, wtf_ptr, bias, logits);
    }
}

// round 11
// speedup vs baseline: 1.0127x; 1.0127x over previous
#include <cuda_runtime.h>
#include <cuda_bf16.h>
#include <cstdint>
#include <cstddef>

// ---------------------------------------------------------------------------
// SupervisedTEMTransition on GB300 (sm_103a), round 6 (resubmit after infra
// failure in round 9 — kernel unchanged, measurement still pending).
//
// R3-R5: cls GEMM tensor pinned ~55% across 3 tilings -> binder is in-order
// issue phase lockstep: per ks-step each warp does [LDS phase][MMA phase],
// phases serialize (LDS of next ks can't issue before current MMAs).
// R6: software-pipelined fragment double buffering: issue LDS(ks+1) before
// MMA(ks); LDS issue+latency hides under the 512-cyc MMA pipe phase.
// Tile 256x128, 8 warps = 4x2 of 64x64 (lowest smem traffic variant).
// bin/trans/wround unchanged.
// ---------------------------------------------------------------------------

#define BATCH_MAX   16384
#define G_TOTAL     768
#define NUM_STATES  4096
#define N_ACTIONS   4

__device__ int   d_perm[BATCH_MAX];
__device__ int   d_off[N_ACTIONS + 1];
__device__ float d_gnext[(size_t)BATCH_MAX * G_TOTAL];       // tf32-rounded A
__device__ float d_wtf32[(size_t)NUM_STATES * G_TOTAL];      // tf32-rounded W

__device__ __forceinline__ uint32_t smem_u32(const void* p) {
    uint32_t a;
    asm("{ .reg .u64 t; cvta.to.shared.u64 t, %1; cvt.u32.u64 %0, t; }"
        : "=r"(a) : "l"(p));
    return a;
}

__device__ __forceinline__ float tf32_rna(float x) {
    float r;
    asm("cvt.rna.tf32.f32 %0, %1;" : "=f"(r) : "f"(x));
    return r;
}

// ---------------------------------------------------------------------------
// Kernel 1: bin rows by action
// ---------------------------------------------------------------------------
__global__ void bin_kernel(const int* __restrict__ act, int B) {
    __shared__ int cnt[N_ACTIONS];
    __shared__ int base[N_ACTIONS];
    int t = threadIdx.x;
    if (t < N_ACTIONS) cnt[t] = 0;
    __syncthreads();
    for (int b = t; b < B; b += blockDim.x) atomicAdd(&cnt[act[b]], 1);
    __syncthreads();
    if (t == 0) {
        int s = 0;
        for (int a = 0; a < N_ACTIONS; a++) { base[a] = s; d_off[a] = s; s += cnt[a]; }
        d_off[N_ACTIONS] = s;
    }
    __syncthreads();
    if (t < N_ACTIONS) cnt[t] = 0;
    __syncthreads();
    for (int b = t; b < B; b += blockDim.x) {
        int a = act[b];
        int p = base[a] + atomicAdd(&cnt[a], 1);
        d_perm[p] = b;
    }
}

// ---------------------------------------------------------------------------
// Kernel 2: routed transition (fp32-exact math; dual-write epilogue)
// ---------------------------------------------------------------------------
__global__ __launch_bounds__(256)
void trans_kernel(const float* __restrict__ emb,
                  const int*   __restrict__ state,
                  const float* __restrict__ D0, const float* __restrict__ D1,
                  const float* __restrict__ D2, const float* __restrict__ D3,
                  float* __restrict__ gdst,      // tf32-rounded scratch
                  float* __restrict__ gout,      // exact fp32 d_out tail
                  int B)
{
    __shared__ float Gs[16][68];
    __shared__ float Ds[16][68];
    __shared__ int   srow[64];
    __shared__ int   sb[64];

    const int a = blockIdx.z >> 2;
    const int f = blockIdx.z & 3;
    const int nf   = (f < 2) ? 256 : 128;
    const int moff = (f == 0) ? 0 : (f == 1) ? 256 : (f == 2) ? 512 : 640;
    const int j0 = blockIdx.x * 64;
    if (j0 >= nf) return;
    const int start = d_off[a];
    const int cnt   = d_off[a + 1] - start;
    const int r0 = blockIdx.y * 64;
    if (r0 >= cnt) return;

    const float* Dbank = (f == 0) ? D0 : (f == 1) ? D1 : (f == 2) ? D2 : D3;
    const float* Dm = Dbank + (size_t)a * nf * nf;

    const int tid = threadIdx.x;
    if (tid < 64) {
        int rr = r0 + tid;
        if (rr < cnt) {
            int bidx = d_perm[start + rr];
            sb[tid]   = bidx;
            srow[tid] = state[bidx] * G_TOTAL;
        } else {
            sb[tid] = -1; srow[tid] = -1;
        }
    }
    __syncthreads();

    const int lm  = tid >> 2;
    const int lk4 = (tid & 3) * 4;
    const int tr  = tid >> 4;
    const int tc  = tid & 15;

    float acc[4][4] = {};

    for (int k0 = 0; k0 < nf; k0 += 16) {
        float4 gv = make_float4(0.f, 0.f, 0.f, 0.f);
        int sr = srow[lm];
        if (sr >= 0)
            gv = *(const float4*)(emb + sr + moff + k0 + lk4);
        float4 dv = *(const float4*)(Dm + (size_t)(j0 + lm) * nf + k0 + lk4);

        Gs[lk4 + 0][lm] = gv.x; Gs[lk4 + 1][lm] = gv.y;
        Gs[lk4 + 2][lm] = gv.z; Gs[lk4 + 3][lm] = gv.w;
        Ds[lk4 + 0][lm] = dv.x; Ds[lk4 + 1][lm] = dv.y;
        Ds[lk4 + 2][lm] = dv.z; Ds[lk4 + 3][lm] = dv.w;
        __syncthreads();

        #pragma unroll
        for (int k = 0; k < 16; k++) {
            float4 av = *(const float4*)&Gs[k][tr * 4];
            float4 bv = *(const float4*)&Ds[k][tc * 4];
            float ar[4] = {av.x, av.y, av.z, av.w};
            float br[4] = {bv.x, bv.y, bv.z, bv.w};
            #pragma unroll
            for (int i = 0; i < 4; i++)
                #pragma unroll
                for (int j = 0; j < 4; j++)
                    acc[i][j] = fmaf(ar[i], br[j], acc[i][j]);
        }
        __syncthreads();
    }

    #pragma unroll
    for (int i = 0; i < 4; i++) {
        int m = tr * 4 + i;
        int bidx = sb[m];
        if (bidx < 0) continue;
        const float* grow = emb + srow[m] + moff + j0 + tc * 4;
        size_t obase = (size_t)bidx * G_TOTAL + moff + j0 + tc * 4;
        #pragma unroll
        for (int j = 0; j < 4; j++) {
            float v = grow[j] + acc[i][j];
            v = fminf(fmaxf(v, -1.0f), 1.0f);
            gdst[obase + j] = tf32_rna(v);
            if (gout) gout[obase + j] = v;
        }
    }
}

// ---------------------------------------------------------------------------
// Kernel 3: tf32-round W
// ---------------------------------------------------------------------------
__global__ __launch_bounds__(256)
void wround_kernel(const float* __restrict__ W, float* __restrict__ Wo) {
    int i = (blockIdx.x * 256 + threadIdx.x) * 4;
    float4 v = *(const float4*)(W + i);
    v.x = tf32_rna(v.x); v.y = tf32_rna(v.y);
    v.z = tf32_rna(v.z); v.w = tf32_rna(v.w);
    *(float4*)(Wo + i) = v;
}

// ---------------------------------------------------------------------------
// Kernel 4: tf32 mma.sync classifier GEMM, software-pipelined fragments.
//   CTA tile 256(M) x 128(N); 8 warps = 4(M) x 2(N) of 64x64 warp tiles.
//   K chunks of 32 (4 ks-steps), 3-stage cp.async ring, 1 sync per chunk.
//   Fragment regs double-buffered: LDS(ks+1) issued before MMA(ks).
// ---------------------------------------------------------------------------
#define AKP          36                       // padded row length (floats)
#define A_FLOATS     (256 * AKP)              // 9216
#define B_FLOATS     (128 * AKP)              // 4608
#define STAGE_FLOATS (A_FLOATS + B_FLOATS)    // 13824 floats (55296 B)
#define STAGES       3
#define CHUNKS       24
#define CLS_DYN_SMEM (STAGES * STAGE_FLOATS * 4)   // 165888 B

extern __shared__ float cls_sm[];

__device__ __forceinline__ void cp16(uint32_t saddr, const float* g) {
    asm volatile("cp.async.cg.shared.global [%0], [%1], 16;"
                 :: "r"(saddr), "l"(g) : "memory");
}

__global__ __launch_bounds__(256, 1)
void cls_mma_kernel(const float* __restrict__ A,     // [16384,768] tf32-rounded
                    const float* __restrict__ W,     // [4096,768] tf32-rounded
                    const float* __restrict__ bias,
                    float* __restrict__ C)
{
    __shared__ float bias_s[128];

    const int tid = threadIdx.x;
    const int n0 = blockIdx.x * 128;
    const int m0 = blockIdx.y * 256;

    if (tid < 128) bias_s[tid] = bias[n0 + tid];

    const int lane = tid & 31;
    const int wid  = tid >> 5;
    const int g    = lane >> 2;       // groupID 0..7
    const int tg   = lane & 3;        // threadID_in_group 0..3
    const int wm   = (wid >> 1) * 64; // warp M offset 0/64/128/192
    const int wn   = (wid & 1) * 64;  // warp N offset 0/64

    // cp.async map: A 2048 float4 (8/thread), B 1024 float4 (4/thread)
    const int lrow = tid >> 3;        // 0..31
    const int lcol = tid & 7;         // 0..7
    const float* gA = A + (size_t)(m0 + lrow) * G_TOTAL + lcol * 4;
    const float* gB = W + (size_t)(n0 + lrow) * G_TOTAL + lcol * 4;
    const uint32_t sA0 = lrow * AKP + lcol * 4;            // floats
    const uint32_t sB0 = A_FLOATS + sA0;

    const uint32_t sbase = smem_u32(cls_sm);

    #define ISSUE_CHUNK(c)                                                     \
        do {                                                                   \
            uint32_t _st = sbase + ((c) % STAGES) * (STAGE_FLOATS * 4);        \
            _Pragma("unroll")                                                  \
            for (int i = 0; i < 8; i++)                                        \
                cp16(_st + (sA0 + i * 32 * AKP) * 4,                           \
                     gA + (size_t)i * 32 * G_TOTAL + (c) * 32);                \
            _Pragma("unroll")                                                  \
            for (int i = 0; i < 4; i++)                                        \
                cp16(_st + (sB0 + i * 32 * AKP) * 4,                           \
                     gB + (size_t)i * 32 * G_TOTAL + (c) * 32);                \
            asm volatile("cp.async.commit_group;" ::: "memory");               \
        } while (0)

    ISSUE_CHUNK(0);
    ISSUE_CHUNK(1);

    float acc[4][8][4] = {};   // [mt 16-row][nt 8-col][frag] = 128 regs
    uint32_t afr[2][4][4];     // double-buffered A frags
    uint32_t bfr[2][8][2];     // double-buffered B frags

    // fragment base offsets (within a stage) for this thread
    const int aoff = (wm + g) * AKP + tg;     // + mt*16*AKP + ks*8
    const int boff = (wn + g) * AKP + tg;     // + nt*8*AKP  + ks*8

    #define LOAD_FRAGS(sAp, sBp, ks, buf)                                      \
        do {                                                                   \
            _Pragma("unroll")                                                  \
            for (int mt = 0; mt < 4; mt++) {                                   \
                const uint32_t* ap =                                           \
                    (const uint32_t*)((sAp) + aoff + mt * 16 * AKP + (ks) * 8);\
                afr[buf][mt][0] = ap[0];                                       \
                afr[buf][mt][1] = ap[8 * AKP];                                 \
                afr[buf][mt][2] = ap[4];                                       \
                afr[buf][mt][3] = ap[8 * AKP + 4];                             \
            }                                                                  \
            _Pragma("unroll")                                                  \
            for (int nt = 0; nt < 8; nt++) {                                   \
                const uint32_t* bp =                                           \
                    (const uint32_t*)((sBp) + boff + nt * 8 * AKP + (ks) * 8); \
                bfr[buf][nt][0] = bp[0];                                       \
                bfr[buf][nt][1] = bp[4];                                       \
            }                                                                  \
        } while (0)

    for (int c = 0; c < CHUNKS; c++) {
        if (c < CHUNKS - 1)
            asm volatile("cp.async.wait_group 1;" ::: "memory");
        else
            asm volatile("cp.async.wait_group 0;" ::: "memory");
        __syncthreads();

        if (c + 2 < CHUNKS)
            ISSUE_CHUNK(c + 2);

        const float* sAp = cls_sm + (c % STAGES) * STAGE_FLOATS;
        const float* sBp = sAp + A_FLOATS;

        LOAD_FRAGS(sAp, sBp, 0, 0);

        #pragma unroll
        for (int ks = 0; ks < 4; ks++) {
            // prefetch next ks fragments BEFORE this ks's MMAs (issue overlap)
            if (ks < 3)
                LOAD_FRAGS(sAp, sBp, ks + 1, (ks + 1) & 1);

            const int cur = ks & 1;
            #pragma unroll
            for (int mt = 0; mt < 4; mt++)
                #pragma unroll
                for (int nt = 0; nt < 8; nt++) {
                    asm volatile(
                        "mma.sync.aligned.m16n8k8.row.col.f32.tf32.tf32.f32 "
                        "{%0,%1,%2,%3}, {%4,%5,%6,%7}, {%8,%9}, {%0,%1,%2,%3};"
                        : "+f"(acc[mt][nt][0]), "+f"(acc[mt][nt][1]),
                          "+f"(acc[mt][nt][2]), "+f"(acc[mt][nt][3])
                        : "r"(afr[cur][mt][0]), "r"(afr[cur][mt][1]),
                          "r"(afr[cur][mt][2]), "r"(afr[cur][mt][3]),
                          "r"(bfr[cur][nt][0]), "r"(bfr[cur][nt][1]));
                }
        }
    }
    #undef ISSUE_CHUNK
    #undef LOAD_FRAGS

    // epilogue: bias + store
    #pragma unroll
    for (int mt = 0; mt < 4; mt++) {
        int r_lo = m0 + wm + mt * 16 + g;
        float* C0 = C + (size_t)r_lo * NUM_STATES + n0;
        float* C1 = C + (size_t)(r_lo + 8) * NUM_STATES + n0;
        #pragma unroll
        for (int nt = 0; nt < 8; nt++) {
            int nc = wn + nt * 8 + tg * 2;
            float b0 = bias_s[nc], b1 = bias_s[nc + 1];
            *(float2*)(C0 + nc) = make_float2(acc[mt][nt][0] + b0, acc[mt][nt][1] + b1);
            *(float2*)(C1 + nc) = make_float2(acc[mt][nt][2] + b0, acc[mt][nt][3] + b1);
        }
    }
}

// ---------------------------------------------------------------------------
// Launch
// ---------------------------------------------------------------------------
extern "C" void kernel_launch(void* const* d_in, const int* in_sizes, int n_in,
                              void* d_out, int out_size)
{
    const int*   state = (const int*)d_in[0];
    const int*   act   = (const int*)d_in[1];
    const float* emb   = (const float*)d_in[2];

    const float *D0, *D1, *D2, *D3, *W, *bias;
    if (in_sizes[3] == NUM_STATES * G_TOTAL) {
        W  = (const float*)d_in[3];
        bias = (const float*)d_in[4];
        D0 = (const float*)d_in[5];
        D1 = (const float*)d_in[6];
        D2 = (const float*)d_in[7];
        D3 = (const float*)d_in[8];
    } else {
        D0 = (const float*)d_in[3];
        D1 = (const float*)d_in[4];
        D2 = (const float*)d_in[5];
        D3 = (const float*)d_in[6];
        W  = (const float*)d_in[7];
        bias = (const float*)d_in[8];
    }

    const int B = in_sizes[0];
    float* out = (float*)d_out;

    float* logits = out;
    float* gout = nullptr;
    if ((size_t)out_size >= (size_t)B * (NUM_STATES + G_TOTAL))
        gout = out + (size_t)B * NUM_STATES;

    float* gnext_ptr = nullptr;
    float* wtf_ptr = nullptr;
    cudaGetSymbolAddress((void**)&gnext_ptr, d_gnext);
    cudaGetSymbolAddress((void**)&wtf_ptr, d_wtf32);

    cudaFuncSetAttribute(cls_mma_kernel,
                         cudaFuncAttributeMaxDynamicSharedMemorySize, CLS_DYN_SMEM);

    // 1) bin rows by action
    bin_kernel<<<1, 1024>>>(act, B);

    // 2) routed transition -> exact g_next (out tail) + tf32-rounded scratch
    {
        dim3 grid(4, (B + 63) / 64, 16);
        trans_kernel<<<grid, 256>>>(emb, state, D0, D1, D2, D3,
                                    gnext_ptr, gout, B);
    }

    // 3) tf32-round W
    wround_kernel<<<(NUM_STATES * G_TOTAL / 4) / 256, 256>>>(W, wtf_ptr);

    // 4) tf32 tensor-core classifier GEMM
    {
        dim3 grid(NUM_STATES / 128, B / 256);
        cls_mma_kernel<<<grid, 256, CLS_DYN_SMEM>>>(gnext_ptr, wtf_ptr, bias, logits);
    }
}

// round 12
// speedup vs baseline: 1.1311x; 1.1169x over previous
#include <cuda_runtime.h>
#include <cuda_bf16.h>
#include <cstdint>
#include <cstddef>

// ---------------------------------------------------------------------------
// SupervisedTEMTransition on GB300 (sm_103a), round 7.
//   - trans rewritten on tf32 mma.sync (was FFMA-bound ~160us -> ~55us)
//   - cls reverted to best-measured R4 config (2 CTA/SM) + per-warp ks stagger
//   - bin_kernel warp-aggregated atomics
// ---------------------------------------------------------------------------

#define BATCH_MAX   16384
#define G_TOTAL     768
#define NUM_STATES  4096
#define N_ACTIONS   4

__device__ int   d_perm[BATCH_MAX];
__device__ int   d_off[N_ACTIONS + 1];
__device__ float d_gnext[(size_t)BATCH_MAX * G_TOTAL];       // tf32-rounded A
__device__ float d_wtf32[(size_t)NUM_STATES * G_TOTAL];      // tf32-rounded W
__device__ float d_embtf[(size_t)NUM_STATES * G_TOTAL];      // tf32-rounded emb
__device__ float d_dtf[655360];                              // tf32-rounded D banks

__device__ __forceinline__ uint32_t smem_u32(const void* p) {
    uint32_t a;
    asm("{ .reg .u64 t; cvta.to.shared.u64 t, %1; cvt.u32.u64 %0, t; }"
        : "=r"(a) : "l"(p));
    return a;
}

__device__ __forceinline__ float tf32_rna(float x) {
    float r;
    asm("cvt.rna.tf32.f32 %0, %1;" : "=f"(r) : "f"(x));
    return r;
}

__device__ __forceinline__ void cp16(uint32_t saddr, const float* g) {
    asm volatile("cp.async.cg.shared.global [%0], [%1], 16;"
                 :: "r"(saddr), "l"(g) : "memory");
}

// ---------------------------------------------------------------------------
// Kernel 0: generic tf32 rounding pass (float4 per thread)
// ---------------------------------------------------------------------------
__global__ __launch_bounds__(256)
void round_kernel(const float* __restrict__ src, float* __restrict__ dst) {
    int i = (blockIdx.x * 256 + threadIdx.x) * 4;
    float4 v = *(const float4*)(src + i);
    v.x = tf32_rna(v.x); v.y = tf32_rna(v.y);
    v.z = tf32_rna(v.z); v.w = tf32_rna(v.w);
    *(float4*)(dst + i) = v;
}

// ---------------------------------------------------------------------------
// Kernel 1: bin rows by action (warp-aggregated atomics)
// ---------------------------------------------------------------------------
__global__ void bin_kernel(const int* __restrict__ act, int B) {
    __shared__ int cnt[N_ACTIONS];
    __shared__ int base[N_ACTIONS];
    int t = threadIdx.x;
    int lane = t & 31;
    if (t < N_ACTIONS) cnt[t] = 0;
    __syncthreads();
    for (int b = t; b < B; b += blockDim.x) {
        int a = act[b];
        #pragma unroll
        for (int aa = 0; aa < N_ACTIONS; aa++) {
            unsigned m = __ballot_sync(0xffffffffu, a == aa);
            if (m && lane == (__ffs(m) - 1))
                atomicAdd(&cnt[aa], __popc(m));
        }
    }
    __syncthreads();
    if (t == 0) {
        int s = 0;
        for (int a = 0; a < N_ACTIONS; a++) { base[a] = s; d_off[a] = s; s += cnt[a]; }
        d_off[N_ACTIONS] = s;
    }
    __syncthreads();
    if (t < N_ACTIONS) cnt[t] = 0;
    __syncthreads();
    for (int b = t; b < B; b += blockDim.x) {
        int a = act[b];
        int mypos = 0;
        #pragma unroll
        for (int aa = 0; aa < N_ACTIONS; aa++) {
            unsigned m = __ballot_sync(0xffffffffu, a == aa);
            if (m) {
                int leader = __ffs(m) - 1;
                int bw = 0;
                if (lane == leader) bw = atomicAdd(&cnt[aa], __popc(m));
                bw = __shfl_sync(0xffffffffu, bw, leader);
                if (a == aa) mypos = bw + __popc(m & ((1u << lane) - 1u));
            }
        }
        d_perm[base[a] + mypos] = b;
    }
}

// ---------------------------------------------------------------------------
// Kernel 2: routed transition on tf32 mma.sync.
//   Per (action, module-f): delta[M,N] = G[M,K] @ D_a[N,K]^T, tile 128x128,
//   K chunks of 32, 3-stage cp.async ring, 8 warps = 2(M) x 4(N) of 64x32.
//   Epilogue: g_next = clip(g_exact + delta); dual write (exact + tf32).
// ---------------------------------------------------------------------------
#define TKP          36
#define T_A_FLOATS   (128 * TKP)
#define T_STAGE      (2 * 128 * TKP)          // 9216 floats (36864 B)
#define T_STAGES     3
#define T_DYN_SMEM   (T_STAGES * T_STAGE * 4) // 110592 B

extern __shared__ float dyn_sm[];

template<int NF>
__global__ __launch_bounds__(256, 2)
void trans_mma_kernel(const float* __restrict__ embtf,  // rounded emb
                      const float* __restrict__ embx,   // exact emb
                      const int*   __restrict__ state,
                      const float* __restrict__ Dtf,    // rounded D bank (this f)
                      int moff,
                      float* __restrict__ gdst,
                      float* __restrict__ gout)
{
    constexpr int NK = NF / 32;                // K chunks
    __shared__ int srow[128];
    __shared__ int sb[128];

    const int a  = blockIdx.z;
    const int n0 = blockIdx.x * 128;
    const int r0 = blockIdx.y * 128;
    const int start = d_off[a];
    const int cnt   = d_off[a + 1] - start;
    if (r0 >= cnt) return;

    const float* Da = Dtf + (size_t)a * NF * NF;
    const int tid = threadIdx.x;

    if (tid < 128) {
        int rr = r0 + tid;
        if (rr < cnt) {
            int bidx = d_perm[start + rr];
            sb[tid] = bidx;
            srow[tid] = state[bidx] * G_TOTAL;
        } else {
            sb[tid] = -1;
            srow[tid] = 0;
        }
    }
    __syncthreads();

    // cp.async map: 4 A units + 4 B units per thread
    const float* pa[4];
    const float* pb[4];
    uint32_t sa[4], sbo[4];
    #pragma unroll
    for (int i = 0; i < 4; i++) {
        int u = tid + i * 256;
        int r = u >> 3, c = u & 7;
        pa[i] = embtf + srow[r] + moff + c * 4;
        pb[i] = Da + (size_t)(n0 + r) * NF + c * 4;
        sa[i]  = (r * TKP + c * 4) * 4;
        sbo[i] = (T_A_FLOATS + r * TKP + c * 4) * 4;
    }

    const uint32_t sbase = smem_u32(dyn_sm);

    #define T_ISSUE(c)                                                         \
        do {                                                                   \
            uint32_t _st = sbase + ((c) % T_STAGES) * (T_STAGE * 4);           \
            _Pragma("unroll")                                                  \
            for (int i = 0; i < 4; i++) cp16(_st + sa[i],  pa[i] + (c) * 32);  \
            _Pragma("unroll")                                                  \
            for (int i = 0; i < 4; i++) cp16(_st + sbo[i], pb[i] + (c) * 32);  \
            asm volatile("cp.async.commit_group;" ::: "memory");               \
        } while (0)

    T_ISSUE(0);
    T_ISSUE(1);

    const int lane = tid & 31;
    const int wid  = tid >> 5;
    const int g    = lane >> 2;
    const int tg   = lane & 3;
    const int wm   = (wid >> 2) * 64;   // 0/64
    const int wn   = (wid & 3) * 32;    // 0..96

    float acc[4][4][4] = {};

    #pragma unroll
    for (int c = 0; c < NK; c++) {
        if (c < NK - 1)
            asm volatile("cp.async.wait_group 1;" ::: "memory");
        else
            asm volatile("cp.async.wait_group 0;" ::: "memory");
        __syncthreads();

        if (c + 2 < NK) T_ISSUE(c + 2);

        const float* sAp = dyn_sm + (c % T_STAGES) * T_STAGE;
        const float* sBp = sAp + T_A_FLOATS;

        #pragma unroll
        for (int ks = 0; ks < 4; ks++) {
            uint32_t af[4][4];
            #pragma unroll
            for (int mt = 0; mt < 4; mt++) {
                const uint32_t* ap =
                    (const uint32_t*)(sAp + (wm + mt * 16 + g) * TKP + ks * 8 + tg);
                af[mt][0] = ap[0];
                af[mt][1] = ap[8 * TKP];
                af[mt][2] = ap[4];
                af[mt][3] = ap[8 * TKP + 4];
            }
            uint32_t bf[4][2];
            #pragma unroll
            for (int nt = 0; nt < 4; nt++) {
                const uint32_t* bp =
                    (const uint32_t*)(sBp + (wn + nt * 8 + g) * TKP + ks * 8 + tg);
                bf[nt][0] = bp[0];
                bf[nt][1] = bp[4];
            }
            #pragma unroll
            for (int mt = 0; mt < 4; mt++)
                #pragma unroll
                for (int nt = 0; nt < 4; nt++) {
                    asm volatile(
                        "mma.sync.aligned.m16n8k8.row.col.f32.tf32.tf32.f32 "
                        "{%0,%1,%2,%3}, {%4,%5,%6,%7}, {%8,%9}, {%0,%1,%2,%3};"
                        : "+f"(acc[mt][nt][0]), "+f"(acc[mt][nt][1]),
                          "+f"(acc[mt][nt][2]), "+f"(acc[mt][nt][3])
                        : "r"(af[mt][0]), "r"(af[mt][1]),
                          "r"(af[mt][2]), "r"(af[mt][3]),
                          "r"(bf[nt][0]), "r"(bf[nt][1]));
                }
        }
    }
    #undef T_ISSUE

    // epilogue: g_next = clip(g_exact + delta), dual write
    #pragma unroll
    for (int mt = 0; mt < 4; mt++) {
        #pragma unroll
        for (int half = 0; half < 2; half++) {
            int rr = wm + mt * 16 + g + half * 8;
            int bidx = sb[rr];
            if (bidx < 0) continue;
            int sr = srow[rr];
            #pragma unroll
            for (int nt = 0; nt < 4; nt++) {
                int col = moff + n0 + wn + nt * 8 + tg * 2;
                float2 gv = *(const float2*)(embx + sr + col);
                float v0 = gv.x + acc[mt][nt][half * 2 + 0];
                float v1 = gv.y + acc[mt][nt][half * 2 + 1];
                v0 = fminf(fmaxf(v0, -1.0f), 1.0f);
                v1 = fminf(fmaxf(v1, -1.0f), 1.0f);
                size_t ob = (size_t)bidx * G_TOTAL + col;
                *(float2*)(gdst + ob) = make_float2(tf32_rna(v0), tf32_rna(v1));
                if (gout)
                    *(float2*)(gout + ob) = make_float2(v0, v1);
            }
        }
    }
}

// ---------------------------------------------------------------------------
// Kernel 3: tf32 mma.sync classifier GEMM (R4 best-measured config + stagger).
//   CTA tile 128x128, 2 CTAs/SM, 8 warps x (64x32), 3-stage cp.async ring,
//   one __syncthreads per chunk, per-warp ks rotation to break phase lockstep.
// ---------------------------------------------------------------------------
#define AKP          36
#define A_FLOATS     (128 * AKP)
#define STAGE_FLOATS (2 * 128 * AKP)          // 9216 floats
#define STAGES       3
#define CHUNKS       24
#define CLS_DYN_SMEM (STAGES * STAGE_FLOATS * 4)   // 110592 B

__global__ __launch_bounds__(256, 2)
void cls_mma_kernel(const float* __restrict__ A,
                    const float* __restrict__ W,
                    const float* __restrict__ bias,
                    float* __restrict__ C)
{
    __shared__ float bias_s[128];

    const int tid = threadIdx.x;
    const int n0 = blockIdx.x * 128;
    const int m0 = blockIdx.y * 128;

    if (tid < 128) bias_s[tid] = bias[n0 + tid];

    const int lane = tid & 31;
    const int wid  = tid >> 5;
    const int g    = lane >> 2;
    const int tg   = lane & 3;
    const int wm   = (wid >> 2) * 64;
    const int wn   = (wid & 3) * 32;

    const int lrow = tid >> 3;
    const int lcol = tid & 7;
    const float* gA = A + (size_t)(m0 + lrow) * G_TOTAL + lcol * 4;
    const float* gB = W + (size_t)(n0 + lrow) * G_TOTAL + lcol * 4;
    const uint32_t sA0 = lrow * AKP + lcol * 4;
    const uint32_t sB0 = A_FLOATS + sA0;

    const uint32_t sbase = smem_u32(dyn_sm);

    #define ISSUE_CHUNK(c)                                                     \
        do {                                                                   \
            uint32_t _st = sbase + ((c) % STAGES) * (STAGE_FLOATS * 4);        \
            _Pragma("unroll")                                                  \
            for (int i = 0; i < 4; i++)                                        \
                cp16(_st + (sA0 + i * 32 * AKP) * 4,                           \
                     gA + (size_t)i * 32 * G_TOTAL + (c) * 32);                \
            _Pragma("unroll")                                                  \
            for (int i = 0; i < 4; i++)                                        \
                cp16(_st + (sB0 + i * 32 * AKP) * 4,                           \
                     gB + (size_t)i * 32 * G_TOTAL + (c) * 32);                \
            asm volatile("cp.async.commit_group;" ::: "memory");               \
        } while (0)

    ISSUE_CHUNK(0);
    ISSUE_CHUNK(1);

    float acc[4][4][4] = {};

    for (int c = 0; c < CHUNKS; c++) {
        if (c < CHUNKS - 1)
            asm volatile("cp.async.wait_group 1;" ::: "memory");
        else
            asm volatile("cp.async.wait_group 0;" ::: "memory");
        __syncthreads();

        if (c + 2 < CHUNKS)
            ISSUE_CHUNK(c + 2);

        const float* sAp = dyn_sm + (c % STAGES) * STAGE_FLOATS;
        const float* sBp = sAp + A_FLOATS;

        #pragma unroll
        for (int kk = 0; kk < 4; kk++) {
            const int ks = (kk + wid) & 3;     // per-warp stagger
            uint32_t a[4][4];
            #pragma unroll
            for (int mt = 0; mt < 4; mt++) {
                const uint32_t* ap =
                    (const uint32_t*)(sAp + (wm + mt * 16 + g) * AKP + ks * 8 + tg);
                a[mt][0] = ap[0];
                a[mt][1] = ap[8 * AKP];
                a[mt][2] = ap[4];
                a[mt][3] = ap[8 * AKP + 4];
            }
            uint32_t b[4][2];
            #pragma unroll
            for (int nt = 0; nt < 4; nt++) {
                const uint32_t* bp =
                    (const uint32_t*)(sBp + (wn + nt * 8 + g) * AKP + ks * 8 + tg);
                b[nt][0] = bp[0];
                b[nt][1] = bp[4];
            }
            #pragma unroll
            for (int mt = 0; mt < 4; mt++)
                #pragma unroll
                for (int nt = 0; nt < 4; nt++) {
                    asm volatile(
                        "mma.sync.aligned.m16n8k8.row.col.f32.tf32.tf32.f32 "
                        "{%0,%1,%2,%3}, {%4,%5,%6,%7}, {%8,%9}, {%0,%1,%2,%3};"
                        : "+f"(acc[mt][nt][0]), "+f"(acc[mt][nt][1]),
                          "+f"(acc[mt][nt][2]), "+f"(acc[mt][nt][3])
                        : "r"(a[mt][0]), "r"(a[mt][1]), "r"(a[mt][2]), "r"(a[mt][3]),
                          "r"(b[nt][0]), "r"(b[nt][1]));
                }
        }
    }
    #undef ISSUE_CHUNK

    #pragma unroll
    for (int mt = 0; mt < 4; mt++) {
        int r_lo = m0 + wm + mt * 16 + g;
        float* C0 = C + (size_t)r_lo * NUM_STATES + n0;
        float* C1 = C + (size_t)(r_lo + 8) * NUM_STATES + n0;
        #pragma unroll
        for (int nt = 0; nt < 4; nt++) {
            int nc = wn + nt * 8 + tg * 2;
            float b0 = bias_s[nc], b1 = bias_s[nc + 1];
            *(float2*)(C0 + nc) = make_float2(acc[mt][nt][0] + b0, acc[mt][nt][1] + b1);
            *(float2*)(C1 + nc) = make_float2(acc[mt][nt][2] + b0, acc[mt][nt][3] + b1);
        }
    }
}

// ---------------------------------------------------------------------------
// Launch
// ---------------------------------------------------------------------------
extern "C" void kernel_launch(void* const* d_in, const int* in_sizes, int n_in,
                              void* d_out, int out_size)
{
    const int*   state = (const int*)d_in[0];
    const int*   act   = (const int*)d_in[1];
    const float* emb   = (const float*)d_in[2];

    const float *D0, *D1, *D2, *D3, *W, *bias;
    if (in_sizes[3] == NUM_STATES * G_TOTAL) {
        W  = (const float*)d_in[3];
        bias = (const float*)d_in[4];
        D0 = (const float*)d_in[5];
        D1 = (const float*)d_in[6];
        D2 = (const float*)d_in[7];
        D3 = (const float*)d_in[8];
    } else {
        D0 = (const float*)d_in[3];
        D1 = (const float*)d_in[4];
        D2 = (const float*)d_in[5];
        D3 = (const float*)d_in[6];
        W  = (const float*)d_in[7];
        bias = (const float*)d_in[8];
    }

    const int B = in_sizes[0];
    float* out = (float*)d_out;

    float* logits = out;
    float* gout = nullptr;
    if ((size_t)out_size >= (size_t)B * (NUM_STATES + G_TOTAL))
        gout = out + (size_t)B * NUM_STATES;

    float *gnext_ptr, *wtf_ptr, *embtf_ptr, *dtf_ptr;
    cudaGetSymbolAddress((void**)&gnext_ptr, d_gnext);
    cudaGetSymbolAddress((void**)&wtf_ptr, d_wtf32);
    cudaGetSymbolAddress((void**)&embtf_ptr, d_embtf);
    cudaGetSymbolAddress((void**)&dtf_ptr, d_dtf);

    cudaFuncSetAttribute(cls_mma_kernel,
                         cudaFuncAttributeMaxDynamicSharedMemorySize, CLS_DYN_SMEM);
    cudaFuncSetAttribute(trans_mma_kernel<256>,
                         cudaFuncAttributeMaxDynamicSharedMemorySize, T_DYN_SMEM);
    cudaFuncSetAttribute(trans_mma_kernel<128>,
                         cudaFuncAttributeMaxDynamicSharedMemorySize, T_DYN_SMEM);

    // 0) pre-round inputs to tf32
    round_kernel<<<3072, 256>>>(emb, embtf_ptr);             // 4096x768
    round_kernel<<<3072, 256>>>(W, wtf_ptr);                 // 4096x768
    round_kernel<<<256, 256>>>(D0, dtf_ptr);                 // 4x256x256
    round_kernel<<<256, 256>>>(D1, dtf_ptr + 262144);
    round_kernel<<<64,  256>>>(D2, dtf_ptr + 524288);        // 4x128x128
    round_kernel<<<64,  256>>>(D3, dtf_ptr + 589824);

    // 1) bin rows by action
    bin_kernel<<<1, 1024>>>(act, B);

    // 2) routed transition on tensor cores (per module)
    {
        dim3 g256(2, (B + 127) / 128, N_ACTIONS);
        dim3 g128(1, (B + 127) / 128, N_ACTIONS);
        trans_mma_kernel<256><<<g256, 256, T_DYN_SMEM>>>(
            embtf_ptr, emb, state, dtf_ptr,          0,   gnext_ptr, gout);
        trans_mma_kernel<256><<<g256, 256, T_DYN_SMEM>>>(
            embtf_ptr, emb, state, dtf_ptr + 262144, 256, gnext_ptr, gout);
        trans_mma_kernel<128><<<g128, 256, T_DYN_SMEM>>>(
            embtf_ptr, emb, state, dtf_ptr + 524288, 512, gnext_ptr, gout);
        trans_mma_kernel<128><<<g128, 256, T_DYN_SMEM>>>(
            embtf_ptr, emb, state, dtf_ptr + 589824, 640, gnext_ptr, gout);
    }

    // 3) tf32 tensor-core classifier GEMM
    {
        dim3 grid(NUM_STATES / 128, B / 128);
        cls_mma_kernel<<<grid, 256, CLS_DYN_SMEM>>>(gnext_ptr, wtf_ptr, bias, logits);
    }
}

// round 13
// speedup vs baseline: 1.2312x; 1.0885x over previous
#include <cuda_runtime.h>
#include <cuda_bf16.h>
#include <cstdint>
#include <cstddef>

// ---------------------------------------------------------------------------
// SupervisedTEMTransition on GB300 (sm_103a), round 8.
//   - ldmatrix (LDSM) fragment loads in both tensor GEMMs (24 LDS -> 6 LDSM
//     per ks-step; shortens the serialized LDS phase that pinned tensor ~54%)
//   - 6 round launches merged into 1; 4 trans launches merged into 1
//   - numerics identical to R7 (rel_err 3.59e-4)
// ---------------------------------------------------------------------------

#define BATCH_MAX   16384
#define G_TOTAL     768
#define NUM_STATES  4096
#define N_ACTIONS   4

__device__ int   d_perm[BATCH_MAX];
__device__ int   d_off[N_ACTIONS + 1];
__device__ float d_gnext[(size_t)BATCH_MAX * G_TOTAL];       // tf32-rounded A
__device__ float d_wtf32[(size_t)NUM_STATES * G_TOTAL];      // tf32-rounded W
__device__ float d_embtf[(size_t)NUM_STATES * G_TOTAL];      // tf32-rounded emb
__device__ float d_dtf[655360];                              // tf32-rounded D banks

__device__ __forceinline__ uint32_t smem_u32(const void* p) {
    uint32_t a;
    asm("{ .reg .u64 t; cvta.to.shared.u64 t, %1; cvt.u32.u64 %0, t; }"
        : "=r"(a) : "l"(p));
    return a;
}

__device__ __forceinline__ float tf32_rna(float x) {
    float r;
    asm("cvt.rna.tf32.f32 %0, %1;" : "=f"(r) : "f"(x));
    return r;
}

__device__ __forceinline__ void cp16(uint32_t saddr, const float* g) {
    asm volatile("cp.async.cg.shared.global [%0], [%1], 16;"
                 :: "r"(saddr), "l"(g) : "memory");
}

__device__ __forceinline__ void ldsm4(uint32_t addr, uint32_t* r) {
    asm volatile("ldmatrix.sync.aligned.m8n8.x4.shared.b16 {%0,%1,%2,%3}, [%4];"
                 : "=r"(r[0]), "=r"(r[1]), "=r"(r[2]), "=r"(r[3]) : "r"(addr));
}

__device__ __forceinline__ void ldsm2(uint32_t addr, uint32_t* r) {
    asm volatile("ldmatrix.sync.aligned.m8n8.x2.shared.b16 {%0,%1}, [%2];"
                 : "=r"(r[0]), "=r"(r[1]) : "r"(addr));
}

// ---------------------------------------------------------------------------
// Kernel 0: merged tf32 rounding (emb, W, D0..D3 in one launch)
//   blocks [0,3072)      : emb     (float4 idx 0..786431)
//   blocks [3072,6144)   : W
//   blocks [6144,6400)   : D0      (65536 f4)
//   blocks [6400,6656)   : D1
//   blocks [6656,6720)   : D2      (16384 f4)
//   blocks [6720,6784)   : D3
// ---------------------------------------------------------------------------
#define ROUND_BLOCKS 6784

__global__ __launch_bounds__(256)
void round_all_kernel(const float* __restrict__ emb, const float* __restrict__ W,
                      const float* __restrict__ D0, const float* __restrict__ D1,
                      const float* __restrict__ D2, const float* __restrict__ D3,
                      float* __restrict__ embo, float* __restrict__ Wo,
                      float* __restrict__ Do)
{
    int blk = blockIdx.x;
    const float* src;
    float* dst;
    int base;                       // float4 base within segment
    if (blk < 3072)       { src = emb; dst = embo;        base = blk; }
    else if (blk < 6144)  { src = W;   dst = Wo;          base = blk - 3072; }
    else if (blk < 6400)  { src = D0;  dst = Do;          base = blk - 6144; }
    else if (blk < 6656)  { src = D1;  dst = Do + 262144; base = blk - 6400; }
    else if (blk < 6720)  { src = D2;  dst = Do + 524288; base = blk - 6656; }
    else                  { src = D3;  dst = Do + 589824; base = blk - 6720; }

    int i = (base * 256 + threadIdx.x) * 4;
    float4 v = *(const float4*)(src + i);
    v.x = tf32_rna(v.x); v.y = tf32_rna(v.y);
    v.z = tf32_rna(v.z); v.w = tf32_rna(v.w);
    *(float4*)(dst + i) = v;
}

// ---------------------------------------------------------------------------
// Kernel 1: bin rows by action (warp-aggregated atomics)
// ---------------------------------------------------------------------------
__global__ void bin_kernel(const int* __restrict__ act, int B) {
    __shared__ int cnt[N_ACTIONS];
    __shared__ int base[N_ACTIONS];
    int t = threadIdx.x;
    int lane = t & 31;
    if (t < N_ACTIONS) cnt[t] = 0;
    __syncthreads();
    for (int b = t; b < B; b += blockDim.x) {
        int a = act[b];
        #pragma unroll
        for (int aa = 0; aa < N_ACTIONS; aa++) {
            unsigned m = __ballot_sync(0xffffffffu, a == aa);
            if (m && lane == (__ffs(m) - 1))
                atomicAdd(&cnt[aa], __popc(m));
        }
    }
    __syncthreads();
    if (t == 0) {
        int s = 0;
        for (int a = 0; a < N_ACTIONS; a++) { base[a] = s; d_off[a] = s; s += cnt[a]; }
        d_off[N_ACTIONS] = s;
    }
    __syncthreads();
    if (t < N_ACTIONS) cnt[t] = 0;
    __syncthreads();
    for (int b = t; b < B; b += blockDim.x) {
        int a = act[b];
        int mypos = 0;
        #pragma unroll
        for (int aa = 0; aa < N_ACTIONS; aa++) {
            unsigned m = __ballot_sync(0xffffffffu, a == aa);
            if (m) {
                int leader = __ffs(m) - 1;
                int bw = 0;
                if (lane == leader) bw = atomicAdd(&cnt[aa], __popc(m));
                bw = __shfl_sync(0xffffffffu, bw, leader);
                if (a == aa) mypos = bw + __popc(m & ((1u << lane) - 1u));
            }
        }
        d_perm[base[a] + mypos] = b;
    }
}

// ---------------------------------------------------------------------------
// Kernel 2: merged routed transition on tf32 mma.sync + LDSM.
//   blockIdx.z = a*4 + f. Tile 128x128, K chunks of 32, 3-stage cp.async,
//   8 warps = 2(M) x 4(N) of 64x32. Epilogue: clip(g_exact + delta).
// ---------------------------------------------------------------------------
#define TKP          36
#define T_A_FLOATS   (128 * TKP)
#define T_STAGE      (2 * 128 * TKP)          // 9216 floats (36864 B)
#define T_STAGES     3
#define T_DYN_SMEM   (T_STAGES * T_STAGE * 4) // 110592 B

extern __shared__ float dyn_sm[];

__global__ __launch_bounds__(256, 2)
void trans_mma_kernel(const float* __restrict__ embtf,
                      const float* __restrict__ embx,
                      const int*   __restrict__ state,
                      const float* __restrict__ Dtf_all,
                      float* __restrict__ gdst,
                      float* __restrict__ gout)
{
    const int a = blockIdx.z >> 2;
    const int f = blockIdx.z & 3;
    const int nf   = (f < 2) ? 256 : 128;
    const int moff = (f == 0) ? 0 : (f == 1) ? 256 : (f == 2) ? 512 : 640;
    const int doff = (f == 0) ? 0 : (f == 1) ? 262144 : (f == 2) ? 524288 : 589824;

    const int n0 = blockIdx.x * 128;
    if (n0 >= nf) return;
    const int r0 = blockIdx.y * 128;
    const int start = d_off[a];
    const int cnt   = d_off[a + 1] - start;
    if (r0 >= cnt) return;

    const int nk = nf / 32;
    const float* Da = Dtf_all + doff + (size_t)a * nf * nf;
    const int tid = threadIdx.x;

    __shared__ int srow[128];
    __shared__ int sb[128];
    if (tid < 128) {
        int rr = r0 + tid;
        if (rr < cnt) {
            int bidx = d_perm[start + rr];
            sb[tid] = bidx;
            srow[tid] = state[bidx] * G_TOTAL;
        } else {
            sb[tid] = -1;
            srow[tid] = 0;
        }
    }
    __syncthreads();

    // cp.async map: 4 A units + 4 B units per thread
    const float* pa[4];
    const float* pb[4];
    uint32_t sa[4], sbo[4];
    #pragma unroll
    for (int i = 0; i < 4; i++) {
        int u = tid + i * 256;
        int r = u >> 3, c = u & 7;
        pa[i] = embtf + srow[r] + moff + c * 4;
        pb[i] = Da + (size_t)(n0 + r) * nf + c * 4;
        sa[i]  = (r * TKP + c * 4) * 4;
        sbo[i] = (T_A_FLOATS + r * TKP + c * 4) * 4;
    }

    const uint32_t sbase = smem_u32(dyn_sm);

    #define T_ISSUE(c)                                                         \
        do {                                                                   \
            uint32_t _st = sbase + ((c) % T_STAGES) * (T_STAGE * 4);           \
            _Pragma("unroll")                                                  \
            for (int i = 0; i < 4; i++) cp16(_st + sa[i],  pa[i] + (c) * 32);  \
            _Pragma("unroll")                                                  \
            for (int i = 0; i < 4; i++) cp16(_st + sbo[i], pb[i] + (c) * 32);  \
            asm volatile("cp.async.commit_group;" ::: "memory");               \
        } while (0)

    T_ISSUE(0);
    T_ISSUE(1);

    const int lane = tid & 31;
    const int wid  = tid >> 5;
    const int g    = lane >> 2;
    const int tg   = lane & 3;
    const int wm   = (wid >> 2) * 64;   // 0/64
    const int wn   = (wid & 3) * 32;    // 0..96

    // LDSM per-lane byte offsets (within a stage)
    const uint32_t aoff =
        ((wm + (lane & 7) + ((lane >> 3) & 1) * 8) * TKP + ((lane >> 4) * 4)) * 4;
    const uint32_t boff =
        T_A_FLOATS * 4 + ((wn + (lane & 7)) * TKP + ((lane >> 3) & 1) * 4) * 4;

    float acc[4][4][4] = {};

    for (int c = 0; c < nk; c++) {
        if (c < nk - 1)
            asm volatile("cp.async.wait_group 1;" ::: "memory");
        else
            asm volatile("cp.async.wait_group 0;" ::: "memory");
        __syncthreads();

        if (c + 2 < nk) T_ISSUE(c + 2);

        const uint32_t st = sbase + (c % T_STAGES) * (T_STAGE * 4);

        #pragma unroll
        for (int ks = 0; ks < 4; ks++) {
            uint32_t af[4][4];
            #pragma unroll
            for (int mt = 0; mt < 4; mt++)
                ldsm4(st + aoff + mt * (16 * TKP * 4) + ks * 32, af[mt]);
            uint32_t bf[4][2];
            #pragma unroll
            for (int nt = 0; nt < 4; nt++)
                ldsm2(st + boff + nt * (8 * TKP * 4) + ks * 32, bf[nt]);
            #pragma unroll
            for (int mt = 0; mt < 4; mt++)
                #pragma unroll
                for (int nt = 0; nt < 4; nt++) {
                    asm volatile(
                        "mma.sync.aligned.m16n8k8.row.col.f32.tf32.tf32.f32 "
                        "{%0,%1,%2,%3}, {%4,%5,%6,%7}, {%8,%9}, {%0,%1,%2,%3};"
                        : "+f"(acc[mt][nt][0]), "+f"(acc[mt][nt][1]),
                          "+f"(acc[mt][nt][2]), "+f"(acc[mt][nt][3])
                        : "r"(af[mt][0]), "r"(af[mt][1]),
                          "r"(af[mt][2]), "r"(af[mt][3]),
                          "r"(bf[nt][0]), "r"(bf[nt][1]));
                }
        }
    }
    #undef T_ISSUE

    // epilogue: g_next = clip(g_exact + delta), dual write
    #pragma unroll
    for (int mt = 0; mt < 4; mt++) {
        #pragma unroll
        for (int half = 0; half < 2; half++) {
            int rr = wm + mt * 16 + g + half * 8;
            int bidx = sb[rr];
            if (bidx < 0) continue;
            int sr = srow[rr];
            #pragma unroll
            for (int nt = 0; nt < 4; nt++) {
                int col = moff + n0 + wn + nt * 8 + tg * 2;
                float2 gv = *(const float2*)(embx + sr + col);
                float v0 = gv.x + acc[mt][nt][half * 2 + 0];
                float v1 = gv.y + acc[mt][nt][half * 2 + 1];
                v0 = fminf(fmaxf(v0, -1.0f), 1.0f);
                v1 = fminf(fmaxf(v1, -1.0f), 1.0f);
                size_t ob = (size_t)bidx * G_TOTAL + col;
                *(float2*)(gdst + ob) = make_float2(tf32_rna(v0), tf32_rna(v1));
                if (gout)
                    *(float2*)(gout + ob) = make_float2(v0, v1);
            }
        }
    }
}

// ---------------------------------------------------------------------------
// Kernel 3: tf32 mma.sync classifier GEMM (2 CTA/SM config + LDSM + stagger).
// ---------------------------------------------------------------------------
#define AKP          36
#define A_FLOATS     (128 * AKP)
#define STAGE_FLOATS (2 * 128 * AKP)
#define STAGES       3
#define CHUNKS       24
#define CLS_DYN_SMEM (STAGES * STAGE_FLOATS * 4)   // 110592 B

__global__ __launch_bounds__(256, 2)
void cls_mma_kernel(const float* __restrict__ A,
                    const float* __restrict__ W,
                    const float* __restrict__ bias,
                    float* __restrict__ C)
{
    __shared__ float bias_s[128];

    const int tid = threadIdx.x;
    const int n0 = blockIdx.x * 128;
    const int m0 = blockIdx.y * 128;

    if (tid < 128) bias_s[tid] = bias[n0 + tid];

    const int lane = tid & 31;
    const int wid  = tid >> 5;
    const int g    = lane >> 2;
    const int tg   = lane & 3;
    const int wm   = (wid >> 2) * 64;
    const int wn   = (wid & 3) * 32;

    const int lrow = tid >> 3;
    const int lcol = tid & 7;
    const float* gA = A + (size_t)(m0 + lrow) * G_TOTAL + lcol * 4;
    const float* gB = W + (size_t)(n0 + lrow) * G_TOTAL + lcol * 4;
    const uint32_t sA0 = lrow * AKP + lcol * 4;
    const uint32_t sB0 = A_FLOATS + sA0;

    const uint32_t sbase = smem_u32(dyn_sm);

    // LDSM per-lane byte offsets
    const uint32_t aoff =
        ((wm + (lane & 7) + ((lane >> 3) & 1) * 8) * AKP + ((lane >> 4) * 4)) * 4;
    const uint32_t boff =
        A_FLOATS * 4 + ((wn + (lane & 7)) * AKP + ((lane >> 3) & 1) * 4) * 4;

    #define ISSUE_CHUNK(c)                                                     \
        do {                                                                   \
            uint32_t _st = sbase + ((c) % STAGES) * (STAGE_FLOATS * 4);        \
            _Pragma("unroll")                                                  \
            for (int i = 0; i < 4; i++)                                        \
                cp16(_st + (sA0 + i * 32 * AKP) * 4,                           \
                     gA + (size_t)i * 32 * G_TOTAL + (c) * 32);                \
            _Pragma("unroll")                                                  \
            for (int i = 0; i < 4; i++)                                        \
                cp16(_st + (sB0 + i * 32 * AKP) * 4,                           \
                     gB + (size_t)i * 32 * G_TOTAL + (c) * 32);                \
            asm volatile("cp.async.commit_group;" ::: "memory");               \
        } while (0)

    ISSUE_CHUNK(0);
    ISSUE_CHUNK(1);

    float acc[4][4][4] = {};

    for (int c = 0; c < CHUNKS; c++) {
        if (c < CHUNKS - 1)
            asm volatile("cp.async.wait_group 1;" ::: "memory");
        else
            asm volatile("cp.async.wait_group 0;" ::: "memory");
        __syncthreads();

        if (c + 2 < CHUNKS)
            ISSUE_CHUNK(c + 2);

        const uint32_t st = sbase + (c % STAGES) * (STAGE_FLOATS * 4);

        #pragma unroll
        for (int kk = 0; kk < 4; kk++) {
            const int ks = (kk + wid) & 3;     // per-warp stagger
            uint32_t a[4][4];
            #pragma unroll
            for (int mt = 0; mt < 4; mt++)
                ldsm4(st + aoff + mt * (16 * AKP * 4) + ks * 32, a[mt]);
            uint32_t b[4][2];
            #pragma unroll
            for (int nt = 0; nt < 4; nt++)
                ldsm2(st + boff + nt * (8 * AKP * 4) + ks * 32, b[nt]);
            #pragma unroll
            for (int mt = 0; mt < 4; mt++)
                #pragma unroll
                for (int nt = 0; nt < 4; nt++) {
                    asm volatile(
                        "mma.sync.aligned.m16n8k8.row.col.f32.tf32.tf32.f32 "
                        "{%0,%1,%2,%3}, {%4,%5,%6,%7}, {%8,%9}, {%0,%1,%2,%3};"
                        : "+f"(acc[mt][nt][0]), "+f"(acc[mt][nt][1]),
                          "+f"(acc[mt][nt][2]), "+f"(acc[mt][nt][3])
                        : "r"(a[mt][0]), "r"(a[mt][1]), "r"(a[mt][2]), "r"(a[mt][3]),
                          "r"(b[nt][0]), "r"(b[nt][1]));
                }
        }
    }
    #undef ISSUE_CHUNK

    #pragma unroll
    for (int mt = 0; mt < 4; mt++) {
        int r_lo = m0 + wm + mt * 16 + g;
        float* C0 = C + (size_t)r_lo * NUM_STATES + n0;
        float* C1 = C + (size_t)(r_lo + 8) * NUM_STATES + n0;
        #pragma unroll
        for (int nt = 0; nt < 4; nt++) {
            int nc = wn + nt * 8 + tg * 2;
            float b0 = bias_s[nc], b1 = bias_s[nc + 1];
            *(float2*)(C0 + nc) = make_float2(acc[mt][nt][0] + b0, acc[mt][nt][1] + b1);
            *(float2*)(C1 + nc) = make_float2(acc[mt][nt][2] + b0, acc[mt][nt][3] + b1);
        }
    }
}

// ---------------------------------------------------------------------------
// Launch
// ---------------------------------------------------------------------------
extern "C" void kernel_launch(void* const* d_in, const int* in_sizes, int n_in,
                              void* d_out, int out_size)
{
    const int*   state = (const int*)d_in[0];
    const int*   act   = (const int*)d_in[1];
    const float* emb   = (const float*)d_in[2];

    const float *D0, *D1, *D2, *D3, *W, *bias;
    if (in_sizes[3] == NUM_STATES * G_TOTAL) {
        W  = (const float*)d_in[3];
        bias = (const float*)d_in[4];
        D0 = (const float*)d_in[5];
        D1 = (const float*)d_in[6];
        D2 = (const float*)d_in[7];
        D3 = (const float*)d_in[8];
    } else {
        D0 = (const float*)d_in[3];
        D1 = (const float*)d_in[4];
        D2 = (const float*)d_in[5];
        D3 = (const float*)d_in[6];
        W  = (const float*)d_in[7];
        bias = (const float*)d_in[8];
    }

    const int B = in_sizes[0];
    float* out = (float*)d_out;

    float* logits = out;
    float* gout = nullptr;
    if ((size_t)out_size >= (size_t)B * (NUM_STATES + G_TOTAL))
        gout = out + (size_t)B * NUM_STATES;

    float *gnext_ptr, *wtf_ptr, *embtf_ptr, *dtf_ptr;
    cudaGetSymbolAddress((void**)&gnext_ptr, d_gnext);
    cudaGetSymbolAddress((void**)&wtf_ptr, d_wtf32);
    cudaGetSymbolAddress((void**)&embtf_ptr, d_embtf);
    cudaGetSymbolAddress((void**)&dtf_ptr, d_dtf);

    cudaFuncSetAttribute(cls_mma_kernel,
                         cudaFuncAttributeMaxDynamicSharedMemorySize, CLS_DYN_SMEM);
    cudaFuncSetAttribute(trans_mma_kernel,
                         cudaFuncAttributeMaxDynamicSharedMemorySize, T_DYN_SMEM);

    // 0) pre-round all inputs to tf32 (single launch)
    round_all_kernel<<<ROUND_BLOCKS, 256>>>(emb, W, D0, D1, D2, D3,
                                            embtf_ptr, wtf_ptr, dtf_ptr);

    // 1) bin rows by action
    bin_kernel<<<1, 1024>>>(act, B);

    // 2) merged routed transition on tensor cores
    {
        dim3 grid(2, (B + 127) / 128, 16);
        trans_mma_kernel<<<grid, 256, T_DYN_SMEM>>>(
            embtf_ptr, emb, state, dtf_ptr, gnext_ptr, gout);
    }

    // 3) tf32 tensor-core classifier GEMM
    {
        dim3 grid(NUM_STATES / 128, B / 128);
        cls_mma_kernel<<<grid, 256, CLS_DYN_SMEM>>>(gnext_ptr, wtf_ptr, bias, logits);
    }
}

// round 14
// speedup vs baseline: 2.1355x; 1.7345x over previous
#include <cuda_runtime.h>
#include <cuda_fp16.h>
#include <cstdint>
#include <cstddef>

// ---------------------------------------------------------------------------
// SupervisedTEMTransition on GB300 (sm_103a), round 9.
//   fp16 (m16n8k16) replaces tf32 (m16n8k8) in both GEMMs: same 10-bit
//   mantissa (identical quantization error) at 2x K-depth per MMA. Halves
//   tensor cycles, LDSM traffic, smem and L2 bytes. K-chunks of 64 halve
//   the sync count. Numerics: inputs rounded to fp16, f32 accumulate,
//   exact-fp32 g_next path to d_out unchanged.
// ---------------------------------------------------------------------------

#define BATCH_MAX   16384
#define G_TOTAL     768
#define NUM_STATES  4096
#define N_ACTIONS   4

__device__ int    d_perm[BATCH_MAX];
__device__ int    d_off[N_ACTIONS + 1];
__device__ __half d_gh[(size_t)BATCH_MAX * G_TOTAL];     // fp16 g_next (cls A)
__device__ __half d_wh[(size_t)NUM_STATES * G_TOTAL];    // fp16 W
__device__ __half d_eh[(size_t)NUM_STATES * G_TOTAL];    // fp16 emb
__device__ __half d_dh[655360];                          // fp16 D banks

__device__ __forceinline__ uint32_t smem_u32(const void* p) {
    uint32_t a;
    asm("{ .reg .u64 t; cvta.to.shared.u64 t, %1; cvt.u32.u64 %0, t; }"
        : "=r"(a) : "l"(p));
    return a;
}

__device__ __forceinline__ void cp16(uint32_t saddr, const void* g) {
    asm volatile("cp.async.cg.shared.global [%0], [%1], 16;"
                 :: "r"(saddr), "l"(g) : "memory");
}

__device__ __forceinline__ void ldsm4(uint32_t addr, uint32_t* r) {
    asm volatile("ldmatrix.sync.aligned.m8n8.x4.shared.b16 {%0,%1,%2,%3}, [%4];"
                 : "=r"(r[0]), "=r"(r[1]), "=r"(r[2]), "=r"(r[3]) : "r"(addr));
}

__device__ __forceinline__ void ldsm2(uint32_t addr, uint32_t* r) {
    asm volatile("ldmatrix.sync.aligned.m8n8.x2.shared.b16 {%0,%1}, [%2];"
                 : "=r"(r[0]), "=r"(r[1]) : "r"(addr));
}

#define MMA_F16(acc, a, b)                                                     \
    asm volatile(                                                              \
        "mma.sync.aligned.m16n8k16.row.col.f32.f16.f16.f32 "                   \
        "{%0,%1,%2,%3}, {%4,%5,%6,%7}, {%8,%9}, {%0,%1,%2,%3};"                \
        : "+f"((acc)[0]), "+f"((acc)[1]), "+f"((acc)[2]), "+f"((acc)[3])       \
        : "r"((a)[0]), "r"((a)[1]), "r"((a)[2]), "r"((a)[3]),                  \
          "r"((b)[0]), "r"((b)[1]))

// ---------------------------------------------------------------------------
// Kernel 0: merged fp32 -> fp16 conversion (emb, W, D0..D3). 8 elems/thread.
//   blocks: emb 1536 | W 1536 | D0 128 | D1 128 | D2 32 | D3 32  = 3392
// ---------------------------------------------------------------------------
#define CONV_BLOCKS 3392

__global__ __launch_bounds__(256)
void conv_all_kernel(const float* __restrict__ emb, const float* __restrict__ W,
                     const float* __restrict__ D0, const float* __restrict__ D1,
                     const float* __restrict__ D2, const float* __restrict__ D3,
                     __half* __restrict__ he, __half* __restrict__ hw,
                     __half* __restrict__ hd)
{
    int blk = blockIdx.x;
    const float* src;
    __half* dst;
    int base;
    if (blk < 1536)      { src = emb; dst = he;          base = blk; }
    else if (blk < 3072) { src = W;   dst = hw;          base = blk - 1536; }
    else if (blk < 3200) { src = D0;  dst = hd;          base = blk - 3072; }
    else if (blk < 3328) { src = D1;  dst = hd + 262144; base = blk - 3200; }
    else if (blk < 3360) { src = D2;  dst = hd + 524288; base = blk - 3328; }
    else                 { src = D3;  dst = hd + 589824; base = blk - 3360; }

    int i = (base * 256 + threadIdx.x) * 8;
    float4 v0 = *(const float4*)(src + i);
    float4 v1 = *(const float4*)(src + i + 4);
    __half2 h0 = __floats2half2_rn(v0.x, v0.y);
    __half2 h1 = __floats2half2_rn(v0.z, v0.w);
    __half2 h2 = __floats2half2_rn(v1.x, v1.y);
    __half2 h3 = __floats2half2_rn(v1.z, v1.w);
    uint4 o;
    o.x = *(uint32_t*)&h0; o.y = *(uint32_t*)&h1;
    o.z = *(uint32_t*)&h2; o.w = *(uint32_t*)&h3;
    *(uint4*)(dst + i) = o;
}

// ---------------------------------------------------------------------------
// Kernel 1: bin rows by action (warp-aggregated atomics)
// ---------------------------------------------------------------------------
__global__ void bin_kernel(const int* __restrict__ act, int B) {
    __shared__ int cnt[N_ACTIONS];
    __shared__ int base[N_ACTIONS];
    int t = threadIdx.x;
    int lane = t & 31;
    if (t < N_ACTIONS) cnt[t] = 0;
    __syncthreads();
    for (int b = t; b < B; b += blockDim.x) {
        int a = act[b];
        #pragma unroll
        for (int aa = 0; aa < N_ACTIONS; aa++) {
            unsigned m = __ballot_sync(0xffffffffu, a == aa);
            if (m && lane == (__ffs(m) - 1))
                atomicAdd(&cnt[aa], __popc(m));
        }
    }
    __syncthreads();
    if (t == 0) {
        int s = 0;
        for (int a = 0; a < N_ACTIONS; a++) { base[a] = s; d_off[a] = s; s += cnt[a]; }
        d_off[N_ACTIONS] = s;
    }
    __syncthreads();
    if (t < N_ACTIONS) cnt[t] = 0;
    __syncthreads();
    for (int b = t; b < B; b += blockDim.x) {
        int a = act[b];
        int mypos = 0;
        #pragma unroll
        for (int aa = 0; aa < N_ACTIONS; aa++) {
            unsigned m = __ballot_sync(0xffffffffu, a == aa);
            if (m) {
                int leader = __ffs(m) - 1;
                int bw = 0;
                if (lane == leader) bw = atomicAdd(&cnt[aa], __popc(m));
                bw = __shfl_sync(0xffffffffu, bw, leader);
                if (a == aa) mypos = bw + __popc(m & ((1u << lane) - 1u));
            }
        }
        d_perm[base[a] + mypos] = b;
    }
}

// ---------------------------------------------------------------------------
// Shared GEMM geometry: K-chunk = 64 halves, smem row stride KP = 72 halves
// (144 B; LDSM conflict-free: 36*r mod 32 distinct over 8 rows).
// Stage = 256 rows -> 36864 B; 3 stages = 110592 B; 2 CTAs/SM.
// ---------------------------------------------------------------------------
#define KP           72
#define A_HALFS      (128 * KP)               // 9216
#define STG_HALFS    (2 * 128 * KP)           // 18432
#define STAGES       3
#define DYN_SMEM_B   (STAGES * STG_HALFS * 2) // 110592

extern __shared__ __half dyn_sm[];

// ---------------------------------------------------------------------------
// Kernel 2: merged routed transition, fp16 mma. blockIdx.z = a*4+f.
//   Tile 128x128, K chunks of 64 (nf=256 -> 4, nf=128 -> 2).
//   8 warps = 2(M) x 4(N) of 64x32. Epilogue: clip(g_exact + delta),
//   dual write (fp16 for cls A + exact fp32 to d_out tail).
// ---------------------------------------------------------------------------
__global__ __launch_bounds__(256, 2)
void trans_mma_kernel(const __half* __restrict__ eh,
                      const float*  __restrict__ embx,
                      const int*    __restrict__ state,
                      const __half* __restrict__ dh,
                      __half* __restrict__ gdst,
                      float*  __restrict__ gout)
{
    const int a = blockIdx.z >> 2;
    const int f = blockIdx.z & 3;
    const int nf   = (f < 2) ? 256 : 128;
    const int moff = (f == 0) ? 0 : (f == 1) ? 256 : (f == 2) ? 512 : 640;
    const int doff = (f == 0) ? 0 : (f == 1) ? 262144 : (f == 2) ? 524288 : 589824;

    const int n0 = blockIdx.x * 128;
    if (n0 >= nf) return;
    const int r0 = blockIdx.y * 128;
    const int start = d_off[a];
    const int cnt   = d_off[a + 1] - start;
    if (r0 >= cnt) return;

    const int nk = nf / 64;
    const __half* Da = dh + doff + (size_t)a * nf * nf;
    const int tid = threadIdx.x;

    __shared__ int srow[128];
    __shared__ int sb[128];
    if (tid < 128) {
        int rr = r0 + tid;
        if (rr < cnt) {
            int bidx = d_perm[start + rr];
            sb[tid] = bidx;
            srow[tid] = state[bidx] * G_TOTAL;
        } else {
            sb[tid] = -1;
            srow[tid] = 0;
        }
    }
    __syncthreads();

    // cp.async: per chunk each row is 128 B = 8 x 16B units; 4 A + 4 B /thread
    const __half* pa[4];
    const __half* pb[4];
    uint32_t sa[4], sbo[4];              // smem byte offsets within stage
    #pragma unroll
    for (int i = 0; i < 4; i++) {
        int u = tid + i * 256;           // 0..1023
        int r = u >> 3, c = u & 7;
        pa[i] = eh + srow[r] + moff + c * 8;
        pb[i] = Da + (size_t)(n0 + r) * nf + c * 8;
        sa[i]  = (r * KP + c * 8) * 2;
        sbo[i] = (A_HALFS + r * KP + c * 8) * 2;
    }

    const uint32_t sbase = smem_u32(dyn_sm);

    #define T_ISSUE(c)                                                         \
        do {                                                                   \
            uint32_t _st = sbase + ((c) % STAGES) * (STG_HALFS * 2);           \
            _Pragma("unroll")                                                  \
            for (int i = 0; i < 4; i++) cp16(_st + sa[i],  pa[i] + (c) * 64);  \
            _Pragma("unroll")                                                  \
            for (int i = 0; i < 4; i++) cp16(_st + sbo[i], pb[i] + (c) * 64);  \
            asm volatile("cp.async.commit_group;" ::: "memory");               \
        } while (0)

    T_ISSUE(0);
    T_ISSUE(1);

    const int lane = tid & 31;
    const int wid  = tid >> 5;
    const int g    = lane >> 2;
    const int tg   = lane & 3;
    const int wm   = (wid >> 2) * 64;
    const int wn   = (wid & 3) * 32;

    const uint32_t aoff =
        ((wm + (lane & 7) + ((lane >> 3) & 1) * 8) * KP) * 2 + (lane >> 4) * 16;
    const uint32_t boff =
        A_HALFS * 2 + ((wn + (lane & 7)) * KP) * 2 + ((lane >> 3) & 1) * 16;

    float acc[4][4][4] = {};

    for (int c = 0; c < nk; c++) {
        if (c < nk - 1)
            asm volatile("cp.async.wait_group 1;" ::: "memory");
        else
            asm volatile("cp.async.wait_group 0;" ::: "memory");
        __syncthreads();

        if (c + 2 < nk) T_ISSUE(c + 2);

        const uint32_t st = sbase + (c % STAGES) * (STG_HALFS * 2);

        #pragma unroll
        for (int ks = 0; ks < 4; ks++) {     // 4 x k16 = K64
            uint32_t af[4][4];
            #pragma unroll
            for (int mt = 0; mt < 4; mt++)
                ldsm4(st + aoff + mt * (16 * KP * 2) + ks * 32, af[mt]);
            uint32_t bf[4][2];
            #pragma unroll
            for (int nt = 0; nt < 4; nt++)
                ldsm2(st + boff + nt * (8 * KP * 2) + ks * 32, bf[nt]);
            #pragma unroll
            for (int mt = 0; mt < 4; mt++)
                #pragma unroll
                for (int nt = 0; nt < 4; nt++)
                    MMA_F16(acc[mt][nt], af[mt], bf[nt]);
        }
    }
    #undef T_ISSUE

    // epilogue: g_next = clip(g_exact + delta); fp16 + exact fp32 writes
    #pragma unroll
    for (int mt = 0; mt < 4; mt++) {
        #pragma unroll
        for (int half = 0; half < 2; half++) {
            int rr = wm + mt * 16 + g + half * 8;
            int bidx = sb[rr];
            if (bidx < 0) continue;
            int sr = srow[rr];
            #pragma unroll
            for (int nt = 0; nt < 4; nt++) {
                int col = moff + n0 + wn + nt * 8 + tg * 2;
                float2 gv = *(const float2*)(embx + sr + col);
                float v0 = gv.x + acc[mt][nt][half * 2 + 0];
                float v1 = gv.y + acc[mt][nt][half * 2 + 1];
                v0 = fminf(fmaxf(v0, -1.0f), 1.0f);
                v1 = fminf(fmaxf(v1, -1.0f), 1.0f);
                size_t ob = (size_t)bidx * G_TOTAL + col;
                *(__half2*)(gdst + ob) = __floats2half2_rn(v0, v1);
                if (gout)
                    *(float2*)(gout + ob) = make_float2(v0, v1);
            }
        }
    }
}

// ---------------------------------------------------------------------------
// Kernel 3: fp16 classifier GEMM. CTA 128x128, 2 CTA/SM, 8 warps x (64x32),
//   12 K-chunks of 64, 3-stage cp.async ring, LDSM, per-warp ks stagger.
// ---------------------------------------------------------------------------
#define NCHUNK 12

__global__ __launch_bounds__(256, 2)
void cls_mma_kernel(const __half* __restrict__ A,
                    const __half* __restrict__ W,
                    const float*  __restrict__ bias,
                    float* __restrict__ C)
{
    __shared__ float bias_s[128];

    const int tid = threadIdx.x;
    const int n0 = blockIdx.x * 128;
    const int m0 = blockIdx.y * 128;

    if (tid < 128) bias_s[tid] = bias[n0 + tid];

    const int lane = tid & 31;
    const int wid  = tid >> 5;
    const int g    = lane >> 2;
    const int tg   = lane & 3;
    const int wm   = (wid >> 2) * 64;
    const int wn   = (wid & 3) * 32;

    const int lrow = tid >> 3;
    const int lcol = tid & 7;
    const __half* gA = A + (size_t)(m0 + lrow) * G_TOTAL + lcol * 8;
    const __half* gB = W + (size_t)(n0 + lrow) * G_TOTAL + lcol * 8;
    const uint32_t sA0 = (lrow * KP + lcol * 8) * 2;
    const uint32_t sB0 = (A_HALFS + lrow * KP + lcol * 8) * 2;

    const uint32_t sbase = smem_u32(dyn_sm);

    const uint32_t aoff =
        ((wm + (lane & 7) + ((lane >> 3) & 1) * 8) * KP) * 2 + (lane >> 4) * 16;
    const uint32_t boff =
        A_HALFS * 2 + ((wn + (lane & 7)) * KP) * 2 + ((lane >> 3) & 1) * 16;

    #define ISSUE_CHUNK(c)                                                     \
        do {                                                                   \
            uint32_t _st = sbase + ((c) % STAGES) * (STG_HALFS * 2);           \
            _Pragma("unroll")                                                  \
            for (int i = 0; i < 4; i++)                                        \
                cp16(_st + sA0 + i * (32 * KP * 2),                            \
                     gA + (size_t)i * 32 * G_TOTAL + (c) * 64);                \
            _Pragma("unroll")                                                  \
            for (int i = 0; i < 4; i++)                                        \
                cp16(_st + sB0 + i * (32 * KP * 2),                            \
                     gB + (size_t)i * 32 * G_TOTAL + (c) * 64);                \
            asm volatile("cp.async.commit_group;" ::: "memory");               \
        } while (0)

    ISSUE_CHUNK(0);
    ISSUE_CHUNK(1);

    float acc[4][4][4] = {};

    for (int c = 0; c < NCHUNK; c++) {
        if (c < NCHUNK - 1)
            asm volatile("cp.async.wait_group 1;" ::: "memory");
        else
            asm volatile("cp.async.wait_group 0;" ::: "memory");
        __syncthreads();

        if (c + 2 < NCHUNK)
            ISSUE_CHUNK(c + 2);

        const uint32_t st = sbase + (c % STAGES) * (STG_HALFS * 2);

        #pragma unroll
        for (int kk = 0; kk < 4; kk++) {
            const int ks = (kk + wid) & 3;       // per-warp stagger
            uint32_t a[4][4];
            #pragma unroll
            for (int mt = 0; mt < 4; mt++)
                ldsm4(st + aoff + mt * (16 * KP * 2) + ks * 32, a[mt]);
            uint32_t b[4][2];
            #pragma unroll
            for (int nt = 0; nt < 4; nt++)
                ldsm2(st + boff + nt * (8 * KP * 2) + ks * 32, b[nt]);
            #pragma unroll
            for (int mt = 0; mt < 4; mt++)
                #pragma unroll
                for (int nt = 0; nt < 4; nt++)
                    MMA_F16(acc[mt][nt], a[mt], b[nt]);
        }
    }
    #undef ISSUE_CHUNK

    #pragma unroll
    for (int mt = 0; mt < 4; mt++) {
        int r_lo = m0 + wm + mt * 16 + g;
        float* C0 = C + (size_t)r_lo * NUM_STATES + n0;
        float* C1 = C + (size_t)(r_lo + 8) * NUM_STATES + n0;
        #pragma unroll
        for (int nt = 0; nt < 4; nt++) {
            int nc = wn + nt * 8 + tg * 2;
            float b0 = bias_s[nc], b1 = bias_s[nc + 1];
            *(float2*)(C0 + nc) = make_float2(acc[mt][nt][0] + b0, acc[mt][nt][1] + b1);
            *(float2*)(C1 + nc) = make_float2(acc[mt][nt][2] + b0, acc[mt][nt][3] + b1);
        }
    }
}

// ---------------------------------------------------------------------------
// Launch
// ---------------------------------------------------------------------------
extern "C" void kernel_launch(void* const* d_in, const int* in_sizes, int n_in,
                              void* d_out, int out_size)
{
    const int*   state = (const int*)d_in[0];
    const int*   act   = (const int*)d_in[1];
    const float* emb   = (const float*)d_in[2];

    const float *D0, *D1, *D2, *D3, *W, *bias;
    if (in_sizes[3] == NUM_STATES * G_TOTAL) {
        W  = (const float*)d_in[3];
        bias = (const float*)d_in[4];
        D0 = (const float*)d_in[5];
        D1 = (const float*)d_in[6];
        D2 = (const float*)d_in[7];
        D3 = (const float*)d_in[8];
    } else {
        D0 = (const float*)d_in[3];
        D1 = (const float*)d_in[4];
        D2 = (const float*)d_in[5];
        D3 = (const float*)d_in[6];
        W  = (const float*)d_in[7];
        bias = (const float*)d_in[8];
    }

    const int B = in_sizes[0];
    float* out = (float*)d_out;

    float* logits = out;
    float* gout = nullptr;
    if ((size_t)out_size >= (size_t)B * (NUM_STATES + G_TOTAL))
        gout = out + (size_t)B * NUM_STATES;

    __half *gh, *wh, *eh, *dh;
    cudaGetSymbolAddress((void**)&gh, d_gh);
    cudaGetSymbolAddress((void**)&wh, d_wh);
    cudaGetSymbolAddress((void**)&eh, d_eh);
    cudaGetSymbolAddress((void**)&dh, d_dh);

    cudaFuncSetAttribute(cls_mma_kernel,
                         cudaFuncAttributeMaxDynamicSharedMemorySize, DYN_SMEM_B);
    cudaFuncSetAttribute(trans_mma_kernel,
                         cudaFuncAttributeMaxDynamicSharedMemorySize, DYN_SMEM_B);

    // 0) fp32 -> fp16 conversion (single launch)
    conv_all_kernel<<<CONV_BLOCKS, 256>>>(emb, W, D0, D1, D2, D3, eh, wh, dh);

    // 1) bin rows by action
    bin_kernel<<<1, 1024>>>(act, B);

    // 2) merged routed transition (fp16 tensor cores)
    {
        dim3 grid(2, (B + 127) / 128, 16);
        trans_mma_kernel<<<grid, 256, DYN_SMEM_B>>>(eh, emb, state, dh, gh, gout);
    }

    // 3) fp16 classifier GEMM
    {
        dim3 grid(NUM_STATES / 128, B / 128);
        cls_mma_kernel<<<grid, 256, DYN_SMEM_B>>>(gh, wh, bias, logits);
    }
}